// round 8
// baseline (speedup 1.0000x reference)
#include <cuda_runtime.h>
#include <cuda_bf16.h>
#include <cstdint>

// Problem constants (fixed by the reference generator).
#define NN   4096      // nodes
#define BB   2048      // batch
#define LL   128       // latent
#define KK   16        // max fan-in
#define DW   145       // 1 + LL + KK  (weights row length)
#define GKK  129       // 1 + LL       (GEMM K dim)

#define NE      14     // batch elements per CTA (147 CTAs -> one wave)
#define STRIDE  4097   // per-element smem stride: bank = (el + p) mod 32

// Triple-buffered staging ring: CH nodes per chunk, 3 buffers, barrier-synced.
#define CH      5
#define NCH     820                  // ceil(NN / CH); bodies beyond NN are guarded
#define STATE_F (NE * STRIDE)        // 57,358 floats of chain state
#define META_F  (STATE_F + 2)        // 57,360 (16B aligned); 3*CH*32 uints
#define PRE_F   (META_F + 3*CH*32)   // 57,840; 3*CH*16 floats (14 pre, wprev, pad)
#define SMEM_CHAIN_BYTES ((PRE_F + 3*CH*16) * 4)   // 232,320 B <= 232,448 opt-in

// ---------------------------------------------------------------------------
// Scratch (__device__ globals zero-initialized at load; rows >= NN are never
// written, so clamped overrun reads return zeros -> parent 0 / weight 0).
// ---------------------------------------------------------------------------
__device__ float        g_pre[(NN + 8) * BB];     // pre[i*BB+b]
__device__ unsigned int g_meta[(NN + 8) * 32];    // per node: 16 parent idx + 16 w bits (128B)
__device__ float        g_wprev[NN + 8];          // sum of w over slots with parent==i-1

// ---------------------------------------------------------------------------
// Kernel 0: probe (shifts ncu's -s 5 capture slot toward chain_kernel).
// ---------------------------------------------------------------------------
__global__ void probe_kernel()
{
    if (threadIdx.x == 0) g_wprev[NN + 7] = 0.0f;
}

// ---------------------------------------------------------------------------
// Kernel 1: pack per-node metadata (one 128B line per node) + wprev.
// ---------------------------------------------------------------------------
__global__ void pack_meta_kernel(const float* __restrict__ w,
                                 const int*   __restrict__ par)
{
    const int wid = threadIdx.x >> 5;
    const int k   = threadIdx.x & 31;
    const int i   = blockIdx.x * 8 + wid;
    if (i >= NN) return;

    unsigned int v;
    float pw = 0.0f;
    if (k < 16) {
        int p = par[i * KK + k];
        v = (unsigned int)p;
        float wk = w[i * DW + (1 + LL) + k];
        pw = (p == i - 1) ? wk : 0.0f;
    } else {
        v = __float_as_uint(w[i * DW + (1 + LL) + (k - 16)]);
    }
    g_meta[i * 32 + k] = v;

    #pragma unroll
    for (int off = 8; off > 0; off >>= 1)
        pw += __shfl_down_sync(0xffffffffu, pw, off);
    if (k == 0) g_wprev[i] = pw;
}

// ---------------------------------------------------------------------------
// Kernel 2: pre[i][b] = sum_{k=0}^{128} w[i][k] * base[b][k],  base=[1, z].
// ---------------------------------------------------------------------------
#define G_PAD 68
__global__ void gemm_pre_kernel(const float* __restrict__ z,
                                const float* __restrict__ w)
{
    extern __shared__ float smg[];
    float* As = smg;
    float* Zs = smg + GKK * G_PAD;

    const int i0 = blockIdx.y * 64;
    const int b0 = blockIdx.x * 64;
    const int tid = threadIdx.x;

    for (int idx = tid; idx < 64 * GKK; idx += 256) {
        int r = idx / GKK, k = idx - r * GKK;
        As[k * G_PAD + r] = w[(i0 + r) * DW + k];
    }
    for (int idx = tid; idx < 64 * GKK; idx += 256) {
        int c = idx / GKK, k = idx - c * GKK;
        Zs[k * G_PAD + c] = (k == 0) ? 1.0f : z[(b0 + c) * LL + (k - 1)];
    }
    __syncthreads();

    const int tx = tid & 15;
    const int ty = tid >> 4;
    const int ri = ty * 4, ci = tx * 4;

    float acc[4][4];
#pragma unroll
    for (int r = 0; r < 4; r++)
#pragma unroll
        for (int c = 0; c < 4; c++) acc[r][c] = 0.0f;

#pragma unroll 3
    for (int k = 0; k < GKK; k++) {
        float4 a  = *reinterpret_cast<const float4*>(&As[k * G_PAD + ri]);
        float4 zc = *reinterpret_cast<const float4*>(&Zs[k * G_PAD + ci]);
        float av[4] = {a.x, a.y, a.z, a.w};
        float zv[4] = {zc.x, zc.y, zc.z, zc.w};
#pragma unroll
        for (int r = 0; r < 4; r++)
#pragma unroll
            for (int c = 0; c < 4; c++)
                acc[r][c] = fmaf(av[r], zv[c], acc[r][c]);
    }

#pragma unroll
    for (int r = 0; r < 4; r++) {
        float4 o = make_float4(acc[r][0], acc[r][1], acc[r][2], acc[r][3]);
        *reinterpret_cast<float4*>(&g_pre[(size_t)(i0 + ri + r) * BB + b0 + ci]) = o;
    }
}

// ---------------------------------------------------------------------------
// Producer-side chunk stage: warp 1 copies CH nodes of meta (128B each),
// pre (14 floats) and wprev into SMEM buffer (c % 3). Clamped node index
// keeps all global reads in-bounds; clamped rows are zero (never written).
// ---------------------------------------------------------------------------
__device__ __forceinline__ void fill_chunk(float* sm, int c, int b0, int lane)
{
    const int buf   = c % 3;
    const int mbase = c * CH;
    const float4* gm4 = reinterpret_cast<const float4*>(g_meta);
    float4* dst = reinterpret_cast<float4*>(sm + META_F) + buf * (CH * 8);

    for (int idx = lane; idx < CH * 8; idx += 32) {
        int node = mbase + (idx >> 3);
        if (node > NN + 7) node = NN + 7;
        dst[idx] = __ldg(gm4 + (size_t)node * 8 + (idx & 7));
    }
    for (int idx = lane; idx < CH * 16; idx += 32) {
        const int row = idx >> 4, col = idx & 15;
        int node = mbase + row;
        if (node > NN + 7) node = NN + 7;
        float v = 0.0f;
        if (col < 14) {
            int b = b0 + col; if (b >= BB) b = BB - 1;
            v = __ldg(&g_pre[(size_t)node * BB + b]);
        } else if (col == 14) {
            v = __ldg(&g_wprev[node]);
        }
        sm[PRE_F + buf * (CH * 16) + idx] = v;
    }
}

// ---------------------------------------------------------------------------
// Kernel 3: sequential DAG chain, barrier-pipelined producer/consumer.
// Phase c: warp 0 consumes chunk c (peeking chunk c+1 slot 0 for lookahead),
// warp 1 fills chunk c+2; all 4 warps __syncthreads() at each phase end.
// Reader buffers {c,c+1}%3 and writer buffer (c+2)%3 are disjoint -> no
// data races, no spin-waits, no hang risk.
// Stale-read trick: gathers for node m+1 issue BEFORE u[m] is stored; a
// (parent==m) slot reads 0 and is patched next iteration via tprev*wprev.
// ---------------------------------------------------------------------------
__global__ void __launch_bounds__(128, 1)
chain_kernel(float* __restrict__ out)
{
    extern __shared__ float sm[];
    const int tid  = threadIdx.x;
    const int warp = tid >> 5;
    const int lane = tid & 31;
    const int b0   = blockIdx.x * NE;

    for (int j = tid; j < STATE_F; j += 128) sm[j] = 0.0f;
    __syncthreads();

    // Prologue: stage chunks 0 and 1.
    if (warp == 1) {
        fill_chunk(sm, 0, b0, lane);
        fill_chunk(sm, 1, b0, lane);
    }
    __syncthreads();

    if (warp == 0) {
        // ---------------- consumer (runs interleaved with producer) --------
        const int  elc = lane < 14 ? lane : 13;   // lanes 14-31 mirror el 13
        const bool store_ok = (lane < 14);
        float* __restrict__ u = sm + elc * STRIDE;
        const char* mbC = reinterpret_cast<const char*>(sm + META_F);

        int4   P0, P1, P2, P3;
        float4 W0, W1, W2, W3;
        {
            const char* pm = mbC;                  // buffer 0, slot 0 = node 0
            P0 = *reinterpret_cast<const int4*>(pm);
            P1 = *reinterpret_cast<const int4*>(pm + 16);
            P2 = *reinterpret_cast<const int4*>(pm + 32);
            P3 = *reinterpret_cast<const int4*>(pm + 48);
            W0 = *reinterpret_cast<const float4*>(pm + 64);
            W1 = *reinterpret_cast<const float4*>(pm + 80);
            W2 = *reinterpret_cast<const float4*>(pm + 96);
            W3 = *reinterpret_cast<const float4*>(pm + 112);
        }
        float pre_c = sm[PRE_F + elc];
        float wp_c  = sm[PRE_F + 14];
        float g[16];
#pragma unroll
        for (int k = 0; k < 16; k++) g[k] = 0.0f;  // node 0 has no live parents
        float tprev = 0.0f;

#pragma unroll 1
        for (int c = 0; c < NCH; c++) {
            const int buf  = c % 3;
            const int nbuf = (c + 1) % 3;
#pragma unroll
            for (int j = 0; j < CH; j++) {
                const int m = c * CH + j;

                // 1. dot over gathered parents of node m
                float a0 = fmaf(g[0],  W0.x, pre_c);
                float a1 = g[1]  * W0.y;
                float a2 = g[2]  * W0.z;
                float a3 = g[3]  * W0.w;
                a0 = fmaf(g[4],  W1.x, a0);
                a1 = fmaf(g[5],  W1.y, a1);
                a2 = fmaf(g[6],  W1.z, a2);
                a3 = fmaf(g[7],  W1.w, a3);
                a0 = fmaf(g[8],  W2.x, a0);
                a1 = fmaf(g[9],  W2.y, a1);
                a2 = fmaf(g[10], W2.z, a2);
                a3 = fmaf(g[11], W2.w, a3);
                a0 = fmaf(g[12], W3.x, a0);
                a1 = fmaf(g[13], W3.y, a1);
                a2 = fmaf(g[14], W3.z, a2);
                a3 = fmaf(g[15], W3.w, a3);
                float s = (a0 + a1) + (a2 + a3);
                s = fmaf(tprev, wp_c, s);            // patch for parent==m-1

                // 2. meta for node m+1 (same buffer, or next buffer slot 0)
                const int sb = (j == CH - 1) ? nbuf : buf;
                const int ss = (j == CH - 1) ? 0 : j + 1;
                const char* pm = mbC + (sb * CH + ss) * 128;
                P0 = *reinterpret_cast<const int4*>(pm);
                P1 = *reinterpret_cast<const int4*>(pm + 16);
                P2 = *reinterpret_cast<const int4*>(pm + 32);
                P3 = *reinterpret_cast<const int4*>(pm + 48);

                // 3. gathers for node m+1 (BEFORE storing u[m])
                g[0]  = u[P0.x]; g[1]  = u[P0.y]; g[2]  = u[P0.z]; g[3]  = u[P0.w];
                g[4]  = u[P1.x]; g[5]  = u[P1.y]; g[6]  = u[P1.z]; g[7]  = u[P1.w];
                g[8]  = u[P2.x]; g[9]  = u[P2.y]; g[10] = u[P2.z]; g[11] = u[P2.w];
                g[12] = u[P3.x]; g[13] = u[P3.y]; g[14] = u[P3.z]; g[15] = u[P3.w];

                W0 = *reinterpret_cast<const float4*>(pm + 64);
                W1 = *reinterpret_cast<const float4*>(pm + 80);
                W2 = *reinterpret_cast<const float4*>(pm + 96);
                W3 = *reinterpret_cast<const float4*>(pm + 112);
                float pre_n = sm[PRE_F + (sb * CH + ss) * 16 + elc];
                float wp_n  = sm[PRE_F + (sb * CH + ss) * 16 + 14];

                // 4. tanh(s) = 1 - 2/(exp(2s)+1); exact at saturation
                float e, r;
                asm("ex2.approx.f32 %0, %1;" : "=f"(e) : "f"(s * 2.885390082f));
                asm("rcp.approx.f32 %0, %1;" : "=f"(r) : "f"(e + 1.0f));
                float t = fmaf(-2.0f, r, 1.0f);

                // 5. commit (bodies m>=NN are guarded padding)
                if (store_ok && m < NN) u[m] = t;
                tprev = t; pre_c = pre_n; wp_c = wp_n;
            }
            __syncthreads();                         // phase boundary
        }
    } else {
        // ------------- producer (warp 1) + idle warps 2,3 ------------------
#pragma unroll 1
        for (int c = 0; c < NCH; c++) {
            if (warp == 1) fill_chunk(sm, c + 2, b0, lane);
            __syncthreads();                         // phase boundary
        }
    }
    __syncthreads();

    // Cooperative coalesced dump: SMEM -> out[b*NN + i].
    for (int e = 0; e < NE; e++) {
        const int b = blockIdx.x * NE + e;
        if (b >= BB) break;
        const float* __restrict__ us = sm + e * STRIDE;
        for (int j = tid; j < NN; j += 128)
            out[(size_t)b * NN + j] = us[j];
    }
}

// ---------------------------------------------------------------------------
// Launch. Inputs: z f32[2048,128], weights f32[4096,145],
// parent_mask f32[4096,16] (redundant — weights pre-masked), parents i32[4096,16].
// Output: f32[2048, 4096].
// ---------------------------------------------------------------------------
extern "C" void kernel_launch(void* const* d_in, const int* in_sizes, int n_in,
                              void* d_out, int out_size)
{
    const float* z       = (const float*)d_in[0];
    const float* weights = (const float*)d_in[1];
    const int*   parents = (const int*)d_in[3];
    float*       out     = (float*)d_out;

    const int gemm_smem  = 2 * GKK * G_PAD * (int)sizeof(float);   // 70,176 B
    const int chain_smem = SMEM_CHAIN_BYTES;                        // 232,320 B

    cudaFuncSetAttribute(gemm_pre_kernel,
                         cudaFuncAttributeMaxDynamicSharedMemorySize, gemm_smem);
    cudaFuncSetAttribute(chain_kernel,
                         cudaFuncAttributeMaxDynamicSharedMemorySize, chain_smem);

    probe_kernel<<<1, 32>>>();

    pack_meta_kernel<<<(NN + 7) / 8, 256>>>(weights, parents);

    dim3 ggrid(BB / 64, NN / 64);
    gemm_pre_kernel<<<ggrid, 256, gemm_smem>>>(z, weights);

    const int nblocks = (BB + NE - 1) / NE;   // 147
    chain_kernel<<<nblocks, 128, chain_smem>>>(out);
}

// round 9
// speedup vs baseline: 2.4275x; 2.4275x over previous
#include <cuda_runtime.h>
#include <cuda_bf16.h>
#include <cstdint>

// Problem constants (fixed by the reference generator).
#define NN   4096      // nodes
#define BB   2048      // batch
#define LL   128       // latent
#define KK   16        // max fan-in
#define DW   145       // 1 + LL + KK  (weights row length)
#define GKK  129       // 1 + LL       (GEMM K dim)

#define NE      14     // batch elements per CTA (147 CTAs -> one wave)
#define STRIDE  4097   // per-element smem stride: bank = (el + p) mod 32

// Staging ring: CH nodes/chunk, 3 smem buffers, producer reg-pipelined 2 ahead.
#define CH      5
#define NCH     820                  // even; consumer bodies 0..4099 (>=NN guarded)
#define STATE_F (NE * STRIDE)        // 57,358 floats of chain state
#define META_F  (STATE_F + 2)        // 57,360 (byte 229,440, 16B aligned); 3*CH*8 float4
#define PRE_F   (META_F + 3*CH*32)   // 57,840; 3 bufs x (CH*15) floats (14 pre + wprev)
#define SMEM_CHAIN_BYTES ((PRE_F + 3*CH*15 + 4) * 4)   // 232,276 B <= 232,448 opt-in

// ---------------------------------------------------------------------------
// Scratch (__device__ globals zero-initialized at load; rows >= NN are never
// written, so clamped overrun reads return zeros -> parent 0 / weight 0).
// ---------------------------------------------------------------------------
__device__ float        g_pre[(NN + 8) * BB];     // pre[i*BB+b]
__device__ unsigned int g_meta[(NN + 8) * 32];    // per node: 16 parent idx + 16 w bits (128B)
__device__ float        g_wprev[NN + 8];          // sum of w over slots with parent==i-1

// ---------------------------------------------------------------------------
// Kernel 0: probe (shifts ncu's -s 5 capture slot toward chain_kernel).
// ---------------------------------------------------------------------------
__global__ void probe_kernel()
{
    if (threadIdx.x == 0) g_wprev[NN + 7] = 0.0f;
}

// ---------------------------------------------------------------------------
// Kernel 1: pack per-node metadata (one 128B line per node) + wprev.
// ---------------------------------------------------------------------------
__global__ void pack_meta_kernel(const float* __restrict__ w,
                                 const int*   __restrict__ par)
{
    const int wid = threadIdx.x >> 5;
    const int k   = threadIdx.x & 31;
    const int i   = blockIdx.x * 8 + wid;
    if (i >= NN) return;

    unsigned int v;
    float pw = 0.0f;
    if (k < 16) {
        int p = par[i * KK + k];
        v = (unsigned int)p;
        float wk = w[i * DW + (1 + LL) + k];
        pw = (p == i - 1) ? wk : 0.0f;
    } else {
        v = __float_as_uint(w[i * DW + (1 + LL) + (k - 16)]);
    }
    g_meta[i * 32 + k] = v;

    #pragma unroll
    for (int off = 8; off > 0; off >>= 1)
        pw += __shfl_down_sync(0xffffffffu, pw, off);
    if (k == 0) g_wprev[i] = pw;
}

// ---------------------------------------------------------------------------
// Kernel 2: pre[i][b] = sum_{k=0}^{128} w[i][k] * base[b][k],  base=[1, z].
// ---------------------------------------------------------------------------
#define G_PAD 68
__global__ void gemm_pre_kernel(const float* __restrict__ z,
                                const float* __restrict__ w)
{
    extern __shared__ float smg[];
    float* As = smg;
    float* Zs = smg + GKK * G_PAD;

    const int i0 = blockIdx.y * 64;
    const int b0 = blockIdx.x * 64;
    const int tid = threadIdx.x;

    for (int idx = tid; idx < 64 * GKK; idx += 256) {
        int r = idx / GKK, k = idx - r * GKK;
        As[k * G_PAD + r] = w[(i0 + r) * DW + k];
    }
    for (int idx = tid; idx < 64 * GKK; idx += 256) {
        int c = idx / GKK, k = idx - c * GKK;
        Zs[k * G_PAD + c] = (k == 0) ? 1.0f : z[(b0 + c) * LL + (k - 1)];
    }
    __syncthreads();

    const int tx = tid & 15;
    const int ty = tid >> 4;
    const int ri = ty * 4, ci = tx * 4;

    float acc[4][4];
#pragma unroll
    for (int r = 0; r < 4; r++)
#pragma unroll
        for (int c = 0; c < 4; c++) acc[r][c] = 0.0f;

#pragma unroll 3
    for (int k = 0; k < GKK; k++) {
        float4 a  = *reinterpret_cast<const float4*>(&As[k * G_PAD + ri]);
        float4 zc = *reinterpret_cast<const float4*>(&Zs[k * G_PAD + ci]);
        float av[4] = {a.x, a.y, a.z, a.w};
        float zv[4] = {zc.x, zc.y, zc.z, zc.w};
#pragma unroll
        for (int r = 0; r < 4; r++)
#pragma unroll
            for (int c = 0; c < 4; c++)
                acc[r][c] = fmaf(av[r], zv[c], acc[r][c]);
    }

#pragma unroll
    for (int r = 0; r < 4; r++) {
        float4 o = make_float4(acc[r][0], acc[r][1], acc[r][2], acc[r][3]);
        *reinterpret_cast<float4*>(&g_pre[(size_t)(i0 + ri + r) * BB + b0 + ci]) = o;
    }
}

// ---------------------------------------------------------------------------
// Producer helpers: register-staged chunk loads and smem stores.
// Node indices are clamped to NN+7 (zero rows) -> all reads in-bounds.
// ---------------------------------------------------------------------------
__device__ __forceinline__ float prod_pre_load(int mbase, int idx, int b0)
{
    const int row = idx / 15, col = idx - row * 15;
    int node = mbase + row; if (node > NN + 7) node = NN + 7;
    if (col < 14) {
        int b = b0 + col; if (b >= BB) b = BB - 1;
        return __ldg(&g_pre[(size_t)node * BB + b]);
    }
    return __ldg(&g_wprev[node]);
}

__device__ __forceinline__ void prod_ldg(int c_ldg, int b0, int lane,
                                         float4& m0, float4& m1,
                                         float& p0, float& p1, float& p2)
{
    const int mbase = c_ldg * CH;
    const float4* gm4 = reinterpret_cast<const float4*>(g_meta);
    {
        int node = mbase + (lane >> 3); if (node > NN + 7) node = NN + 7;
        m0 = __ldg(gm4 + (size_t)node * 8 + (lane & 7));
    }
    if (lane < 8) {
        int idx = 32 + lane;
        int node = mbase + (idx >> 3); if (node > NN + 7) node = NN + 7;
        m1 = __ldg(gm4 + (size_t)node * 8 + (idx & 7));
    }
    p0 = prod_pre_load(mbase, lane, b0);
    p1 = prod_pre_load(mbase, lane + 32, b0);
    if (lane < 11) p2 = prod_pre_load(mbase, lane + 64, b0);
}

__device__ __forceinline__ void prod_sts(float* sm, int c_sts, int lane,
                                         float4 m0, float4 m1,
                                         float p0, float p1, float p2)
{
    const int buf = c_sts % 3;
    float4* dst = reinterpret_cast<float4*>(sm + META_F) + buf * (CH * 8);
    dst[lane] = m0;
    if (lane < 8) dst[32 + lane] = m1;
    float* pd = sm + PRE_F + buf * (CH * 15);
    pd[lane] = p0;
    pd[lane + 32] = p1;
    if (lane < 11) pd[lane + 64] = p2;
}

// ---------------------------------------------------------------------------
// Kernel 3: sequential DAG chain. 64 threads: warp 0 = consumer (pure-SMEM
// inner loop), warp 1 = producer (reg-pipelined 2 phases deep -> its LDG
// latency never blocks the phase barrier). Triple smem buffer: consumer
// reads chunk c (+peek c+1 slot 0); producer STSes chunk c+2 (disjoint).
// Stale-read trick: gathers for node m+1 issue BEFORE u[m] is stored; a
// (parent==m) slot reads 0 and is patched next iteration via tprev*wprev.
// ---------------------------------------------------------------------------
__global__ void __launch_bounds__(64, 1)
chain_kernel(float* __restrict__ out)
{
    extern __shared__ float sm[];
    const int tid  = threadIdx.x;
    const int warp = tid >> 5;
    const int lane = tid & 31;
    const int b0   = blockIdx.x * NE;

    for (int j = tid; j < STATE_F; j += 64) sm[j] = 0.0f;
    __syncthreads();

    // Prologue: producer fills smem buffers 0..2 and preloads reg set B(=ch3).
    float4 mA0, mA1, mB0, mB1;
    float  pA0 = 0.f, pA1 = 0.f, pA2 = 0.f, pB0 = 0.f, pB1 = 0.f, pB2 = 0.f;
    if (warp == 1) {
        for (int cc = 0; cc < 3; cc++) {
            prod_ldg(cc, b0, lane, mA0, mA1, pA0, pA1, pA2);
            prod_sts(sm, cc, lane, mA0, mA1, pA0, pA1, pA2);
        }
        prod_ldg(3, b0, lane, mB0, mB1, pB0, pB1, pB2);   // set B = chunk 3
    }
    __syncthreads();

    if (warp == 0) {
        // ------------------------------ consumer ---------------------------
        const int  elc = lane < 14 ? lane : 13;    // lanes 14-31 mirror el 13
        const bool store_ok = (lane < 14);
        float* __restrict__ u = sm + elc * STRIDE;
        const char* mbC = reinterpret_cast<const char*>(sm + META_F);

        int4   P0, P1, P2, P3;
        float4 W0, W1, W2, W3;
        {
            const char* pm = mbC;                  // buffer 0, slot 0 = node 0
            P0 = *reinterpret_cast<const int4*>(pm);
            P1 = *reinterpret_cast<const int4*>(pm + 16);
            P2 = *reinterpret_cast<const int4*>(pm + 32);
            P3 = *reinterpret_cast<const int4*>(pm + 48);
            W0 = *reinterpret_cast<const float4*>(pm + 64);
            W1 = *reinterpret_cast<const float4*>(pm + 80);
            W2 = *reinterpret_cast<const float4*>(pm + 96);
            W3 = *reinterpret_cast<const float4*>(pm + 112);
        }
        float pre_c = sm[PRE_F + elc];
        float wp_c  = sm[PRE_F + 14];
        float g[16];
#pragma unroll
        for (int k = 0; k < 16; k++) g[k] = 0.0f;  // node 0 has no live parents
        float tprev = 0.0f;
        int   buf = 0, m = 0;

#pragma unroll 1
        for (int c = 0; c < NCH; c++) {
            const int nbuf = (buf == 2) ? 0 : buf + 1;
            const char* curb = mbC + buf  * (CH * 128);
            const char* nxtb = mbC + nbuf * (CH * 128);
            const float* curp = sm + PRE_F + buf  * (CH * 15);
            const float* nxtp = sm + PRE_F + nbuf * (CH * 15);
#pragma unroll
            for (int j = 0; j < CH; j++) {
                // 1. dot over gathered parents of node m
                float a0 = fmaf(g[0],  W0.x, pre_c);
                float a1 = g[1]  * W0.y;
                float a2 = g[2]  * W0.z;
                float a3 = g[3]  * W0.w;
                a0 = fmaf(g[4],  W1.x, a0);
                a1 = fmaf(g[5],  W1.y, a1);
                a2 = fmaf(g[6],  W1.z, a2);
                a3 = fmaf(g[7],  W1.w, a3);
                a0 = fmaf(g[8],  W2.x, a0);
                a1 = fmaf(g[9],  W2.y, a1);
                a2 = fmaf(g[10], W2.z, a2);
                a3 = fmaf(g[11], W2.w, a3);
                a0 = fmaf(g[12], W3.x, a0);
                a1 = fmaf(g[13], W3.y, a1);
                a2 = fmaf(g[14], W3.z, a2);
                a3 = fmaf(g[15], W3.w, a3);
                float s = (a0 + a1) + (a2 + a3);
                s = fmaf(tprev, wp_c, s);            // patch for parent==m-1

                // 2. meta for node m+1 (same buffer, or next-buffer slot 0)
                const char*  pm = (j < CH - 1) ? curb + (j + 1) * 128 : nxtb;
                const float* pp = (j < CH - 1) ? curp + (j + 1) * 15  : nxtp;
                P0 = *reinterpret_cast<const int4*>(pm);
                P1 = *reinterpret_cast<const int4*>(pm + 16);
                P2 = *reinterpret_cast<const int4*>(pm + 32);
                P3 = *reinterpret_cast<const int4*>(pm + 48);

                // 3. gathers for node m+1 (BEFORE storing u[m])
                g[0]  = u[P0.x]; g[1]  = u[P0.y]; g[2]  = u[P0.z]; g[3]  = u[P0.w];
                g[4]  = u[P1.x]; g[5]  = u[P1.y]; g[6]  = u[P1.z]; g[7]  = u[P1.w];
                g[8]  = u[P2.x]; g[9]  = u[P2.y]; g[10] = u[P2.z]; g[11] = u[P2.w];
                g[12] = u[P3.x]; g[13] = u[P3.y]; g[14] = u[P3.z]; g[15] = u[P3.w];

                W0 = *reinterpret_cast<const float4*>(pm + 64);
                W1 = *reinterpret_cast<const float4*>(pm + 80);
                W2 = *reinterpret_cast<const float4*>(pm + 96);
                W3 = *reinterpret_cast<const float4*>(pm + 112);
                float pre_n = pp[elc];
                float wp_n  = pp[14];

                // 4. tanh(s) = 1 - 2/(exp(2s)+1); exact at saturation
                float e, r;
                asm("ex2.approx.f32 %0, %1;" : "=f"(e) : "f"(s * 2.885390082f));
                asm("rcp.approx.f32 %0, %1;" : "=f"(r) : "f"(e + 1.0f));
                float t = fmaf(-2.0f, r, 1.0f);

                // 5. commit (bodies m>=NN are guarded padding)
                if (store_ok && m < NN) u[m] = t;
                tprev = t; pre_c = pre_n; wp_c = wp_n;
                m++;
            }
            buf = nbuf;
            __syncthreads();                         // phase boundary
        }
    } else {
        // ------------------------------ producer ---------------------------
#pragma unroll 1
        for (int c = 0; c < NCH; c += 2) {
            // even phase c: STS chunk c+2 from set A (loaded at phase c-2);
            // phase 0 skips STS (buffers 0..2 pre-filled).
            if (c > 0) prod_sts(sm, c + 2, lane, mA0, mA1, pA0, pA1, pA2);
            prod_ldg(c + 4, b0, lane, mA0, mA1, pA0, pA1, pA2);
            __syncthreads();
            // odd phase c+1: STS chunk c+3 from set B (loaded at phase c-1).
            prod_sts(sm, c + 3, lane, mB0, mB1, pB0, pB1, pB2);
            prod_ldg(c + 5, b0, lane, mB0, mB1, pB0, pB1, pB2);
            __syncthreads();
        }
    }
    __syncthreads();

    // Cooperative coalesced dump: SMEM -> out[b*NN + i].
    for (int e = 0; e < NE; e++) {
        const int b = blockIdx.x * NE + e;
        if (b >= BB) break;
        const float* __restrict__ us = sm + e * STRIDE;
        for (int j = tid; j < NN; j += 64)
            out[(size_t)b * NN + j] = us[j];
    }
}

// ---------------------------------------------------------------------------
// Launch. Inputs: z f32[2048,128], weights f32[4096,145],
// parent_mask f32[4096,16] (redundant — weights pre-masked), parents i32[4096,16].
// Output: f32[2048, 4096].
// ---------------------------------------------------------------------------
extern "C" void kernel_launch(void* const* d_in, const int* in_sizes, int n_in,
                              void* d_out, int out_size)
{
    const float* z       = (const float*)d_in[0];
    const float* weights = (const float*)d_in[1];
    const int*   parents = (const int*)d_in[3];
    float*       out     = (float*)d_out;

    const int gemm_smem  = 2 * GKK * G_PAD * (int)sizeof(float);   // 70,176 B
    const int chain_smem = SMEM_CHAIN_BYTES;                        // 232,276 B

    cudaFuncSetAttribute(gemm_pre_kernel,
                         cudaFuncAttributeMaxDynamicSharedMemorySize, gemm_smem);
    cudaFuncSetAttribute(chain_kernel,
                         cudaFuncAttributeMaxDynamicSharedMemorySize, chain_smem);

    probe_kernel<<<1, 32>>>();

    pack_meta_kernel<<<(NN + 7) / 8, 256>>>(weights, parents);

    dim3 ggrid(BB / 64, NN / 64);
    gemm_pre_kernel<<<ggrid, 256, gemm_smem>>>(z, weights);

    const int nblocks = (BB + NE - 1) / NE;   // 147
    chain_kernel<<<nblocks, 64, chain_smem>>>(out);
}